// round 8
// baseline (speedup 1.0000x reference)
#include <cuda_runtime.h>
#include <cmath>

#define PITCH 68
#define NB (64 * PITCH)     // floats per std buffer (17408 B)
#define VP 68               // vertical buffer pitch in ull units (32 pair-rows)

typedef unsigned long long ull;

// Host-built tables, passed by value in kernel param space (~9.2 KB).
// trd[t*16+L] = {g0,g0,g1,g1} with g0=g(4L+2t-64), g1=g(4L+2t-63)  (dup-quads)
// sg[i] = g(i-63), i in [0,126]
struct TapParam { float4 trd[34 * 16]; float sg[128]; };

__device__ __forceinline__ ull f2x2(float lo, float hi) {
    ull r; asm("mov.b64 %0, {%1, %2};" : "=l"(r) : "f"(lo), "f"(hi)); return r;
}
__device__ __forceinline__ float2 unpk(ull v) {
    float2 r; asm("mov.b64 {%0, %1}, %2;" : "=f"(r.x), "=f"(r.y) : "l"(v)); return r;
}
__device__ __forceinline__ void ffma2(ull& d, ull a, ull b) {
    asm("fma.rn.f32x2 %0, %1, %2, %0;" : "+l"(d) : "l"(a), "l"(b));
}
__device__ __forceinline__ ull addp(ull a, ull b) {
    ull r; asm("add.rn.f32x2 %0, %1, %2;" : "=l"(r) : "l"(a), "l"(b)); return r;
}
__device__ __forceinline__ ull mulp(ull a, ull b) {
    ull r; asm("mul.rn.f32x2 %0, %1, %2;" : "=l"(r) : "l"(a), "l"(b)); return r;
}

// t[w] = dup g(4L - kb - SH + (w - 7)), w in [0,10]; 6 broadcast LDS.128.
template<int SH>
__device__ __forceinline__ void load_dup_taps(ull t[11], const ulonglong2* __restrict__ TRD,
                                              int kb, int L) {
    const ulonglong2* tp = TRD + (28 - (kb >> 1)) * 16 + L;
    ulonglong2 e[6];
    #pragma unroll
    for (int j = 0; j < 6; j++) e[j] = tp[j * 16];
    #pragma unroll
    for (int w = 0; w <= 10; w++) {
        const int u = w + 1 - SH;
        t[w] = (u & 1) ? e[u >> 1].y : e[u >> 1].x;
    }
}

// Left circulant, std src, col-pair acc (MOV-free):
// acc[r][p] = {dst[4rg+r][c0+2p], dst[4rg+r][c0+2p+1]}, dst = sum_k g(i-k-SH) src[k][:]
template<int SH>
__device__ __forceinline__ void mm_left(ull acc[4][2], const float* __restrict__ src,
                                        const ulonglong2* __restrict__ TRD,
                                        int rg, int c0) {
    #pragma unroll
    for (int r = 0; r < 4; r++) { acc[r][0] = 0ull; acc[r][1] = 0ull; }
    #pragma unroll 1
    for (int kb = 0; kb < 64; kb += 8) {
        ull t[11];
        load_dup_taps<SH>(t, TRD, kb, rg);
        #pragma unroll
        for (int q = 0; q < 8; q++) {
            ulonglong2 s = *(const ulonglong2*)&src[(kb + q) * PITCH + c0];
            #pragma unroll
            for (int r = 0; r < 4; r++) {
                ffma2(acc[r][0], t[r - q + 7], s.x);
                ffma2(acc[r][1], t[r - q + 7], s.y);
            }
        }
    }
}

// Right circulant^T, vertical src, row-pair acc (MOV-free):
// SV[p*VP+k] = {v[2p][k], v[2p+1][k]};  acc[ip][c] = {dst[2(ip0+ip)][c0+c], dst[..+1][c0+c]}
// dst[i][m] = sum_k v[i][k] g(m-k-SH)
template<int SH>
__device__ __forceinline__ void mm_rightV(ull acc[2][4], const ull* __restrict__ SV,
                                          const ulonglong2* __restrict__ TRD,
                                          int ip0, int cg) {
    #pragma unroll
    for (int ip = 0; ip < 2; ip++)
        #pragma unroll
        for (int c = 0; c < 4; c++) acc[ip][c] = 0ull;
    #pragma unroll 1
    for (int kb = 0; kb < 64; kb += 8) {
        ull t[11];
        load_dup_taps<SH>(t, TRD, kb, cg);
        #pragma unroll
        for (int ip = 0; ip < 2; ip++) {
            const ull* row = SV + (ip0 + ip) * VP + kb;
            ulonglong2 s0 = *(const ulonglong2*)&row[0];
            ulonglong2 s1 = *(const ulonglong2*)&row[2];
            ulonglong2 s2 = *(const ulonglong2*)&row[4];
            ulonglong2 s3 = *(const ulonglong2*)&row[6];
            ull sk[8] = {s0.x, s0.y, s1.x, s1.y, s2.x, s2.y, s3.x, s3.y};
            #pragma unroll
            for (int q = 0; q < 8; q++)
                #pragma unroll
                for (int c = 0; c < 4; c++)
                    ffma2(acc[ip][c], sk[q], t[c - q + 7]);
        }
    }
}

__global__ void __launch_bounds__(256, 3)
uppolyact_kernel(const float* __restrict__ xg,
                 const float* __restrict__ coef,
                 float* __restrict__ outg,
                 const TapParam tab) {
    extern __shared__ float sm[];
    float* B0 = sm;                 // x (std)         -> V0: oo^2 (vert)
    float* B1 = sm + NB;            // V1: Gx (vert) -> oe^2 -> B1: tmp (std)
    float* B2 = sm + 2 * NB;        // V2: x (vert) -> xG^T -> eo^2 (vert)
    ull* V0 = (ull*)B0; ull* V1 = (ull*)B1; ull* V2 = (ull*)B2;
    ulonglong2* TRD = (ulonglong2*)(sm + 3 * NB);   // 544 x 16 B
    float* Sg  = (float*)(TRD + 544);  // 128
    float* Pr  = Sg + 128;             // 8 x 68
    float* rs  = Pr + 544;             // 64 (raw)
    float* cs  = rs + 64;              // 64 (raw)
    float* rs1 = cs + 64;              // 64 (raw)
    float* cs2 = rs1 + 64;             // 64 (raw)
    float* tsp = cs2 + 64;             // 1  (raw)

    const int tid = threadIdx.x;
    const int rg = tid >> 4, cg = tid & 15;
    const int r0 = rg << 2, c0 = cg << 2;
    const int ip0 = rg << 1;
    const int lane = tid & 31, wrp = tid >> 5;
    const float* xin = xg + (size_t)blockIdx.x * 4096;
    float* outp = outg + (size_t)blockIdx.x * 4096;
    const float inv64 = 1.0f / 64.0f;

    const float k0 = __ldg(&coef[0]), k1 = __ldg(&coef[1]);
    const float k2q = 0.25f * __ldg(&coef[2]);

    // ==== P0: tables -> smem; x -> std + vertical; rs/cs partials ====
    {
        const float4* tp = tab.trd;  float4* td = (float4*)TRD;
        #pragma unroll
        for (int i = tid; i < 544; i += 256) td[i] = tp[i];
        if (tid < 128) Sg[tid] = tab.sg[tid];
    }
    {
        float4 xv[4];
        #pragma unroll
        for (int r = 0; r < 4; r++) {
            xv[r] = *(const float4*)&xin[(r0 + r) * 64 + c0];
            *(float4*)&B0[(r0 + r) * PITCH + c0] = xv[r];
        }
        #pragma unroll
        for (int ip = 0; ip < 2; ip++) {
            float4 a = xv[2 * ip], b = xv[2 * ip + 1];
            ulonglong2 o0, o1;
            o0.x = f2x2(a.x, b.x); o0.y = f2x2(a.y, b.y);
            o1.x = f2x2(a.z, b.z); o1.y = f2x2(a.w, b.w);
            *(ulonglong2*)&V2[(ip0 + ip) * VP + c0]     = o0;
            *(ulonglong2*)&V2[(ip0 + ip) * VP + c0 + 2] = o1;
        }
        float4 pr;  // alt-sum over this thread's 4 rows, per col
        pr.x = xv[0].x - xv[1].x + xv[2].x - xv[3].x;
        pr.y = xv[0].y - xv[1].y + xv[2].y - xv[3].y;
        pr.z = xv[0].z - xv[1].z + xv[2].z - xv[3].z;
        pr.w = xv[0].w - xv[1].w + xv[2].w - xv[3].w;
        pr.x += __shfl_xor_sync(~0u, pr.x, 16);
        pr.y += __shfl_xor_sync(~0u, pr.y, 16);
        pr.z += __shfl_xor_sync(~0u, pr.z, 16);
        pr.w += __shfl_xor_sync(~0u, pr.w, 16);
        if (lane < 16) *(float4*)&Pr[wrp * 68 + c0] = pr;
        float4 pc;  // alt-sum over this thread's 4 cols, per row
        pc.x = xv[0].x - xv[0].y + xv[0].z - xv[0].w;
        pc.y = xv[1].x - xv[1].y + xv[1].z - xv[1].w;
        pc.z = xv[2].x - xv[2].y + xv[2].z - xv[2].w;
        pc.w = xv[3].x - xv[3].y + xv[3].z - xv[3].w;
        #pragma unroll
        for (int o = 8; o >= 1; o >>= 1) {
            pc.x += __shfl_xor_sync(~0u, pc.x, o);
            pc.y += __shfl_xor_sync(~0u, pc.y, o);
            pc.z += __shfl_xor_sync(~0u, pc.z, o);
            pc.w += __shfl_xor_sync(~0u, pc.w, o);
        }
        if (cg == 0) *(float4*)&cs[r0] = pc;
    }
    __syncthreads();

    // ==== P1: rs reduce + a1 = Gx (left,std) ; a2 = xG^T (rightV,vert) ====
    if (tid < 64) {
        float s = 0.f;
        #pragma unroll
        for (int w = 0; w < 8; w++) s += Pr[w * 68 + tid];
        rs[tid] = s;
    }
    {
        ull a1[4][2];
        mm_left<0>(a1, B0, TRD, rg, c0);
        #pragma unroll
        for (int ip = 0; ip < 2; ip++) {   // repack col-pair -> vertical V1
            float2 l0 = unpk(a1[2 * ip][0]),     l1 = unpk(a1[2 * ip][1]);
            float2 h0 = unpk(a1[2 * ip + 1][0]), h1 = unpk(a1[2 * ip + 1][1]);
            ulonglong2 o0, o1;
            o0.x = f2x2(l0.x, h0.x); o0.y = f2x2(l0.y, h0.y);
            o1.x = f2x2(l1.x, h1.x); o1.y = f2x2(l1.y, h1.y);
            *(ulonglong2*)&V1[(ip0 + ip) * VP + c0]     = o0;
            *(ulonglong2*)&V1[(ip0 + ip) * VP + c0 + 2] = o1;
        }
    }
    {
        ull a2[2][4];
        mm_rightV<0>(a2, V2, TRD, ip0, cg);
        #pragma unroll
        for (int ip = 0; ip < 2; ip++) {   // overwrite V2 with xG^T (vertical)
            ulonglong2 o0, o1;
            o0.x = a2[ip][0]; o0.y = a2[ip][1];
            o1.x = a2[ip][2]; o1.y = a2[ip][3];
            *(ulonglong2*)&V2[(ip0 + ip) * VP + c0]     = o0;
            *(ulonglong2*)&V2[(ip0 + ip) * VP + c0 + 2] = o1;
        }
    }
    __syncthreads();

    // ==== P2a: matvec rank-1 sums (identities) + ts + a3 = (Gx)G^T ====
    if (tid < 64) {                // rs1[j] = sum_k rs[k] g(j-k)
        float acc = 0.f;
        const float* sgj = &Sg[tid + 63];
        for (int k = 0; k < 64; k++) acc = fmaf(rs[k], sgj[-k], acc);
        rs1[tid] = acc;
    } else if (tid < 128) {        // cs2[i] = sum_k g(i-k) cs[k]
        int i = tid - 64;
        float acc = 0.f;
        const float* sgi = &Sg[i + 63];
        for (int k = 0; k < 64; k++) acc = fmaf(sgi[-k], cs[k], acc);
        cs2[i] = acc;
    } else if (tid < 160) {        // ts = sum_j (-1)^j rs[j]
        int l = tid - 128;
        float v = rs[2 * l] - rs[2 * l + 1];
        #pragma unroll
        for (int o = 16; o > 0; o >>= 1) v += __shfl_xor_sync(~0u, v, o);
        if (l == 0) tsp[0] = v;
    }
    ull a3[2][4];
    mm_rightV<0>(a3, V1, TRD, ip0, cg);
    __syncthreads();

    // ==== P2b: corrections + squares (all vertical):  V0<-oo^2 V1<-oe^2 V2<-eo^2 ====
    {
        float4 rv1 = *(const float4*)&rs1[c0];
        ull me[4];
        me[0] = f2x2(rv1.x * inv64, -rv1.x * inv64);
        me[1] = f2x2(rv1.y * inv64, -rv1.y * inv64);
        me[2] = f2x2(rv1.z * inv64, -rv1.z * inv64);
        me[3] = f2x2(rv1.w * inv64, -rv1.w * inv64);
        #pragma unroll
        for (int ip = 0; ip < 2; ip++) {
            int p = ip0 + ip, row = p * VP + c0;
            float c2a = cs2[2 * p] * inv64, c2b = cs2[2 * p + 1] * inv64;
            ull pc = f2x2(c2a, c2b), npc = f2x2(-c2a, -c2b);
            ulonglong2 u0 = *(const ulonglong2*)&V2[row];
            ulonglong2 u1 = *(const ulonglong2*)&V2[row + 2];
            ull e0 = addp(u0.x, me[0]), e1 = addp(u0.y, me[1]);
            ull e2 = addp(u1.x, me[2]), e3 = addp(u1.y, me[3]);
            ulonglong2 q0, q1;
            q0.x = mulp(e0, e0); q0.y = mulp(e1, e1);
            q1.x = mulp(e2, e2); q1.y = mulp(e3, e3);
            *(ulonglong2*)&V2[row]     = q0;
            *(ulonglong2*)&V2[row + 2] = q1;
            ulonglong2 v0 = *(const ulonglong2*)&V1[row];
            ulonglong2 v1 = *(const ulonglong2*)&V1[row + 2];
            ull o0 = addp(v0.x, pc), o1 = addp(v0.y, npc);
            ull o2 = addp(v1.x, pc), o3 = addp(v1.y, npc);
            ulonglong2 w0, w1;
            w0.x = mulp(o0, o0); w0.y = mulp(o1, o1);
            w1.x = mulp(o2, o2); w1.y = mulp(o3, o3);
            *(ulonglong2*)&V1[row]     = w0;
            *(ulonglong2*)&V1[row + 2] = w1;
            ulonglong2 z0, z1;
            z0.x = mulp(a3[ip][0], a3[ip][0]); z0.y = mulp(a3[ip][1], a3[ip][1]);
            z1.x = mulp(a3[ip][2], a3[ip][2]); z1.y = mulp(a3[ip][3], a3[ip][3]);
            *(ulonglong2*)&V0[row]     = z0;
            *(ulonglong2*)&V0[row + 2] = z1;
        }
    }
    __syncthreads();

    // ==== P3: tmp = oe^2 + oo^2 G'^T  -> B1 (std, unpacked) ====
    {
        ull acc[2][4];
        mm_rightV<1>(acc, V0, TRD, ip0, cg);
        #pragma unroll
        for (int ip = 0; ip < 2; ip++) {
            int p = ip0 + ip, row = p * VP + c0;
            ulonglong2 v0 = *(const ulonglong2*)&V1[row];
            ulonglong2 v1 = *(const ulonglong2*)&V1[row + 2];
            float2 u0 = unpk(addp(v0.x, acc[ip][0]));
            float2 u1 = unpk(addp(v0.y, acc[ip][1]));
            float2 u2 = unpk(addp(v1.x, acc[ip][2]));
            float2 u3 = unpk(addp(v1.y, acc[ip][3]));
            *(float4*)&B1[(2 * p) * PITCH + c0]     = make_float4(u0.x, u1.x, u2.x, u3.x);
            *(float4*)&B1[(2 * p + 1) * PITCH + c0] = make_float4(u0.y, u1.y, u2.y, u3.y);
        }
    }
    __syncthreads();

    // ==== P4+P5: F = G'*tmp (left,std) ; E = eo^2 G'^T (rightV) ; combine ====
    {
        ull Fa[4][2], Ea[2][4];
        mm_left<1>(Fa, B1, TRD, rg, c0);
        mm_rightV<1>(Ea, V2, TRD, ip0, cg);
        const float ts = tsp[0];
        const float inv4096 = inv64 * inv64;
        float4 rv = *(const float4*)&rs[c0];
        #pragma unroll
        for (int r = 0; r < 4; r++) {
            int i = r0 + r;
            float sgni = (i & 1) ? -1.f : 1.f;
            float4 xv = *(const float4*)&xin[i * 64 + c0];
            float2 f0 = unpk(Fa[r][0]), f1 = unpk(Fa[r][1]);
            float2 ea = unpk(Ea[r >> 1][0]), eb = unpk(Ea[r >> 1][1]);
            float2 ec = unpk(Ea[r >> 1][2]), ed = unpk(Ea[r >> 1][3]);
            float E0 = (r & 1) ? ea.y : ea.x;
            float E1 = (r & 1) ? eb.y : eb.x;
            float E2 = (r & 1) ? ec.y : ec.x;
            float E3 = (r & 1) ? ed.y : ed.x;
            float csv = cs[i] * inv64;
            float tci = sgni * ts * inv4096;
            float vx = xv.x + sgni * rv.x * inv64 + csv + tci;
            float vy = xv.y + sgni * rv.y * inv64 - csv - tci;
            float vz = xv.z + sgni * rv.z * inv64 + csv + tci;
            float vw = xv.w + sgni * rv.w * inv64 - csv - tci;
            float4 o;
            o.x = k0 + k1 * xv.x + k2q * (vx * vx + E0 + f0.x);
            o.y = k0 + k1 * xv.y + k2q * (vy * vy + E1 + f0.y);
            o.z = k0 + k1 * xv.z + k2q * (vz * vz + E2 + f1.x);
            o.w = k0 + k1 * xv.w + k2q * (vw * vw + E3 + f1.y);
            *(float4*)&outp[i * 64 + c0] = o;
        }
    }
}

// Host-side taps (double precision, exact integer angle reduction; 64-periodic).
static double host_g(int t) {
    const double PI_D = 3.14159265358979323846;
    long long m = 2LL * t + 1;
    int r1 = (int)(((63LL * m) % 256 + 256) % 256); if (r1 >= 128) r1 -= 256;
    int r2 = (int)((m % 256 + 256) % 256);          if (r2 >= 128) r2 -= 256;
    return (sin(PI_D * r1 / 128.0) / sin(PI_D * r2 / 128.0)) / 64.0;
}

extern "C" void kernel_launch(void* const* d_in, const int* in_sizes, int n_in,
                              void* d_out, int out_size) {
    const float* x    = (const float*)d_in[0];
    const float* coef = (const float*)d_in[1];
    float* out = (float*)d_out;

    static TapParam tab;
    static bool tab_init = false;
    if (!tab_init) {
        for (int t = 0; t < 34; t++)
            for (int L = 0; L < 16; L++) {
                float g0 = (float)host_g(4 * L + 2 * t - 64);
                float g1 = (float)host_g(4 * L + 2 * t - 63);
                tab.trd[t * 16 + L] = make_float4(g0, g0, g1, g1);
            }
        for (int i = 0; i < 127; i++) tab.sg[i] = (float)host_g(i - 63);
        tab.sg[127] = 0.f;
        tab_init = true;
    }

    int smem_bytes = 3 * NB * (int)sizeof(float)
                   + 544 * 16
                   + (128 + 544 + 4 * 64 + 4) * (int)sizeof(float);   // ~65 KB
    cudaFuncSetAttribute(uppolyact_kernel,
                         cudaFuncAttributeMaxDynamicSharedMemorySize, smem_bytes);

    int nimg = in_sizes[0] / 4096;   // 4096 images of 64x64
    uppolyact_kernel<<<nimg, 256, smem_bytes>>>(x, coef, out, tab);
}

// round 9
// speedup vs baseline: 1.0425x; 1.0425x over previous
#include <cuda_runtime.h>
#include <cmath>

#define PITCH 68
#define NB (64 * PITCH)   // 4352 floats per padded 64x64 buffer

typedef unsigned long long ull;

// Tap table passed by value (constant bank): TU[m*16+c] as float4 (g0,g1,g1,g2)
// = ulonglong2 { pair(4c+2m-64), pair(4c+2m-63) }, pair(s) = {g(s), g(s+1)}.
struct TapTable { float4 e[34 * 16]; float sg[128]; };

__device__ int g_ctr;
__global__ void zero_ctr_kernel() { g_ctr = 0; }

__device__ __forceinline__ ull f2x2(float lo, float hi) {
    ull r; asm("mov.b64 %0, {%1, %2};" : "=l"(r) : "f"(lo), "f"(hi)); return r;
}
__device__ __forceinline__ float2 unpk(ull v) {
    float2 r; asm("mov.b64 {%0, %1}, %2;" : "=f"(r.x), "=f"(r.y) : "l"(v)); return r;
}
__device__ __forceinline__ void ffma2(ull& d, ull a, ull b) {
    asm("fma.rn.f32x2 %0, %1, %2, %0;" : "+l"(d) : "l"(a), "l"(b));
}

// Load the 10 consecutive tap pairs t[w] (pair-row u0+w, u0 = 57-SH-kb) from TU.
template<int SH>
__device__ __forceinline__ void load_taps(ull t[10], const ulonglong2* __restrict__ TU,
                                          int kb, int lane_idx) {
    const int m0 = 28 - (kb >> 1);
    const ulonglong2* tp = TU + m0 * 16 + lane_idx;
    ulonglong2 e[6];
    #pragma unroll
    for (int j = 0; j < (SH ? 5 : 6); j++) e[j] = tp[j * 16];
    #pragma unroll
    for (int w = 0; w < 10; w++) {
        if (SH) t[w] = (w & 1) ? e[w >> 1].y : e[w >> 1].x;
        else    t[w] = (w & 1) ? e[(w + 1) >> 1].x : e[w >> 1].y;
    }
}

// Right circulant^T: dst[i][m] = sum_k src[i][k] * g(m-k-SH).
// acc[i][p] = packed {dst[r0+i][c0+2p], dst[r0+i][c0+2p+1]}.
template<int SH>
__device__ __forceinline__ void mm_right_core(ull acc[4][2], const float* __restrict__ src,
                                              const ulonglong2* __restrict__ TU,
                                              int r0, int cg) {
    #pragma unroll
    for (int r = 0; r < 4; r++) { acc[r][0] = 0ull; acc[r][1] = 0ull; }
    #pragma unroll 1
    for (int kb = 0; kb < 64; kb += 8) {
        ull t[10];
        load_taps<SH>(t, TU, kb, cg);
        #pragma unroll
        for (int i = 0; i < 4; i++) {
            float4 va = *(const float4*)&src[(r0 + i) * PITCH + kb];
            float4 vb = *(const float4*)&src[(r0 + i) * PITCH + kb + 4];
            float sv[8] = {va.x, va.y, va.z, va.w, vb.x, vb.y, vb.z, vb.w};
            #pragma unroll
            for (int q = 0; q < 8; q++) {
                ull sd = f2x2(sv[q], sv[q]);
                ffma2(acc[i][0], sd, t[7 - q]);
                ffma2(acc[i][1], sd, t[9 - q]);
            }
        }
    }
}

// Left circulant: dst[i][j] = sum_k g(i-k-SH) * src[k][j], row-pair packing:
// acc[rp][c] = packed {dst[r0+2rp][c0+c], dst[r0+2rp+1][c0+c]}.
template<int SH>
__device__ __forceinline__ void mm_leftT_core(ull acc[2][4], const float* __restrict__ src,
                                              const ulonglong2* __restrict__ TU,
                                              int rg, int c0) {
    #pragma unroll
    for (int rp = 0; rp < 2; rp++)
        #pragma unroll
        for (int c = 0; c < 4; c++) acc[rp][c] = 0ull;
    #pragma unroll 1
    for (int kb = 0; kb < 64; kb += 8) {
        ull t[10];
        load_taps<SH>(t, TU, kb, rg);
        #pragma unroll
        for (int q = 0; q < 8; q++) {
            float4 sv = *(const float4*)&src[(kb + q) * PITCH + c0];
            float s[4] = {sv.x, sv.y, sv.z, sv.w};
            #pragma unroll
            for (int c = 0; c < 4; c++) {
                ull sd = f2x2(s[c], s[c]);
                ffma2(acc[0][c], t[7 - q], sd);
                ffma2(acc[1][c], t[9 - q], sd);
            }
        }
    }
}

__device__ __forceinline__ void store_right(float* __restrict__ dst, ull acc[4][2],
                                            int r0, int c0) {
    #pragma unroll
    for (int r = 0; r < 4; r++) {
        ulonglong2 o; o.x = acc[r][0]; o.y = acc[r][1];
        *(ulonglong2*)&dst[(r0 + r) * PITCH + c0] = o;
    }
}

__global__ void __launch_bounds__(256, 3)
uppolyact_kernel(const float* __restrict__ xg,
                 const float* __restrict__ coef,
                 float* __restrict__ outg,
                 const TapTable tab, int nimg) {
    extern __shared__ float sm[];
    float* B0 = sm;            // x -> oo^2
    float* B1 = sm + NB;       // Gx -> oe^2 -> tmp
    float* B2 = sm + 2 * NB;   // xG^T -> eo^2
    ulonglong2* TU = (ulonglong2*)(sm + 3 * NB);  // 544 entries (8704 B)
    float* Pr  = (float*)(TU + 544);  // 16 x 68 partials
    float* Pc  = Pr + 1088;           // 16 x 68 partials
    float* rs  = Pc + 1088;           // 64
    float* cs  = rs + 64;             // 64
    float* rs1 = cs + 64;             // 64
    float* cs2 = rs1 + 64;            // 64
    float* tsp = cs2 + 64;            // 1
    __shared__ int simg;

    const int tid = threadIdx.x;
    const int rg = tid >> 4, cg = tid & 15;
    const int r0 = rg << 2, c0 = cg << 2;

    const float k0 = __ldg(&coef[0]), k1 = __ldg(&coef[1]);
    const float k2q = 0.25f * __ldg(&coef[2]);

    // One-time per CTA: tap table -> smem, first work item
    {
        const ulonglong2* TUp = (const ulonglong2*)tab.e;
        #pragma unroll
        for (int i = tid; i < 544; i += 256) TU[i] = TUp[i];
    }
    if (tid == 0) simg = atomicAdd(&g_ctr, 1);
    __syncthreads();

    while (true) {
        const int img = simg;          // stable: written pre-barrier (init or P2a)
        if (img >= nimg) break;
        const float* xin = xg + (size_t)img * 4096;
        float* outp = outg + (size_t)img * 4096;

        // ---- P0: load image; x rank-1 partials ----
        {
            float4 xv[4];
            #pragma unroll
            for (int r = 0; r < 4; r++) {
                xv[r] = *(const float4*)&xin[(r0 + r) * 64 + c0];
                *(float4*)&B0[(r0 + r) * PITCH + c0] = xv[r];
            }
            float4 pr;   // sum_r (-1)^r x[r][j] partial (r0 even -> sign +)
            pr.x = xv[0].x - xv[1].x + xv[2].x - xv[3].x;
            pr.y = xv[0].y - xv[1].y + xv[2].y - xv[3].y;
            pr.z = xv[0].z - xv[1].z + xv[2].z - xv[3].z;
            pr.w = xv[0].w - xv[1].w + xv[2].w - xv[3].w;
            *(float4*)&Pr[rg * 68 + c0] = pr;
            float4 pc;   // sum_c (-1)^c x[i][c] partial
            pc.x = xv[0].x - xv[0].y + xv[0].z - xv[0].w;
            pc.y = xv[1].x - xv[1].y + xv[1].z - xv[1].w;
            pc.z = xv[2].x - xv[2].y + xv[2].z - xv[2].w;
            pc.w = xv[3].x - xv[3].y + xv[3].z - xv[3].w;
            *(float4*)&Pc[cg * 68 + r0] = pc;
        }
        __syncthreads();

        // ---- P1: rs/cs reduce (tid<64, overlapped) + B1 = Gx ; B2 = xG^T ----
        if (tid < 64) {
            float s = 0.f, t = 0.f;
            #pragma unroll
            for (int g = 0; g < 16; g++) { s += Pr[g * 68 + tid]; t += Pc[g * 68 + tid]; }
            rs[tid] = s; cs[tid] = t;
        }
        {
            ull a1[2][4], a2[4][2];
            mm_leftT_core<0>(a1, B0, TU, rg, c0);
            mm_right_core<0>(a2, B0, TU, r0, cg);
            // rs1 partials: alt row-sums of xG^T (a2, col-pair layout)
            {
                float2 u0 = unpk(a2[0][0]), u1 = unpk(a2[1][0]),
                       u2 = unpk(a2[2][0]), u3 = unpk(a2[3][0]);
                float2 w0 = unpk(a2[0][1]), w1 = unpk(a2[1][1]),
                       w2 = unpk(a2[2][1]), w3 = unpk(a2[3][1]);
                float4 p;
                p.x = u0.x - u1.x + u2.x - u3.x;
                p.y = u0.y - u1.y + u2.y - u3.y;
                p.z = w0.x - w1.x + w2.x - w3.x;
                p.w = w0.y - w1.y + w2.y - w3.y;
                *(float4*)&Pr[rg * 68 + c0] = p;
            }
            // cs2 partials: alt col-sums of Gx (a1, row-pair layout)
            {
                float2 v0 = unpk(a1[0][0]), v1 = unpk(a1[0][1]),
                       v2 = unpk(a1[0][2]), v3 = unpk(a1[0][3]);
                float2 y0 = unpk(a1[1][0]), y1 = unpk(a1[1][1]),
                       y2 = unpk(a1[1][2]), y3 = unpk(a1[1][3]);
                float4 p;
                p.x = v0.x - v1.x + v2.x - v3.x;
                p.y = v0.y - v1.y + v2.y - v3.y;
                p.z = y0.x - y1.x + y2.x - y3.x;
                p.w = y0.y - y1.y + y2.y - y3.y;
                *(float4*)&Pc[cg * 68 + r0] = p;
                #pragma unroll
                for (int rp = 0; rp < 2; rp++) {
                    float2 a = unpk(a1[rp][0]), b = unpk(a1[rp][1]),
                           c = unpk(a1[rp][2]), d = unpk(a1[rp][3]);
                    *(float4*)&B1[(r0 + 2 * rp) * PITCH + c0] =
                        make_float4(a.x, b.x, c.x, d.x);
                    *(float4*)&B1[(r0 + 2 * rp + 1) * PITCH + c0] =
                        make_float4(a.y, b.y, c.y, d.y);
                }
            }
            store_right(B2, a2, r0, c0);
        }
        __syncthreads();

        // ---- P2a: rs1/cs2/ts reduces + NEXT-IMAGE FETCH + oo = (Gx)G^T ----
        if (tid < 64) {
            float s = 0.f, t = 0.f;
            #pragma unroll
            for (int g = 0; g < 16; g++) { s += Pr[g * 68 + tid]; t += Pc[g * 68 + tid]; }
            rs1[tid] = s; cs2[tid] = t;
        } else if (tid < 96) {
            int l = tid - 64;
            float v = rs[2 * l] - rs[2 * l + 1];
            #pragma unroll
            for (int o = 16; o > 0; o >>= 1)
                v += __shfl_xor_sync(~0u, v, o);
            if (l == 0) tsp[0] = v;
        } else if (tid == 96) {
            simg = atomicAdd(&g_ctr, 1);   // published by the P2a barrier
        }
        ull a3[4][2];
        mm_right_core<0>(a3, B1, TU, r0, cg);
        __syncthreads();

        // ---- P2b: corrections + squares: B0<-oo^2 B1<-oe^2 B2<-eo^2 ----
        {
            const float inv64 = 1.0f / 64.0f;
            float4 rv1 = *(const float4*)&rs1[c0];
            #pragma unroll
            for (int r = 0; r < 4; r++) {
                int i = r0 + r;
                float sgni = (i & 1) ? -1.f : 1.f;
                float cs2v = cs2[i] * inv64;
                int base = i * PITCH + c0;
                float4 v1 = *(float4*)&B1[base];
                float4 v2 = *(float4*)&B2[base];
                float2 o0 = unpk(a3[r][0]), o1 = unpk(a3[r][1]);
                float4 eo, oe, oo;
                eo.x = v2.x + sgni * rv1.x * inv64;
                eo.y = v2.y + sgni * rv1.y * inv64;
                eo.z = v2.z + sgni * rv1.z * inv64;
                eo.w = v2.w + sgni * rv1.w * inv64;
                oe.x = v1.x + cs2v;  oe.y = v1.y - cs2v;
                oe.z = v1.z + cs2v;  oe.w = v1.w - cs2v;
                oo.x = o0.x; oo.y = o0.y; oo.z = o1.x; oo.w = o1.y;
                eo.x *= eo.x; eo.y *= eo.y; eo.z *= eo.z; eo.w *= eo.w;
                oe.x *= oe.x; oe.y *= oe.y; oe.z *= oe.z; oe.w *= oe.w;
                oo.x *= oo.x; oo.y *= oo.y; oo.z *= oo.z; oo.w *= oo.w;
                *(float4*)&B2[base] = eo;
                *(float4*)&B1[base] = oe;
                *(float4*)&B0[base] = oo;
            }
        }
        __syncthreads();

        // ---- P3: tmp: B1 = oe^2 + oo^2 G'^T ----
        {
            ull acc[4][2];
            mm_right_core<1>(acc, B0, TU, r0, cg);
            #pragma unroll
            for (int r = 0; r < 4; r++) {
                int base = (r0 + r) * PITCH + c0;
                float4 d = *(float4*)&B1[base];
                float2 a0 = unpk(acc[r][0]), a1 = unpk(acc[r][1]);
                d.x += a0.x;  d.y += a0.y;  d.z += a1.x;  d.w += a1.y;
                *(float4*)&B1[base] = d;
            }
        }
        __syncthreads();

        // ---- P4+P5 fused: F = G'*tmp, E = eo^2 G'^T, final combine ----
        {
            ull Fa[2][4], Ea[4][2];
            mm_leftT_core<1>(Fa, B1, TU, rg, c0);
            mm_right_core<1>(Ea, B2, TU, r0, cg);
            float Ff[4][4];
            #pragma unroll
            for (int rp = 0; rp < 2; rp++)
                #pragma unroll
                for (int c = 0; c < 4; c++) {
                    float2 u = unpk(Fa[rp][c]);
                    Ff[2 * rp][c] = u.x;
                    Ff[2 * rp + 1][c] = u.y;
                }
            const float ts = tsp[0];
            const float inv64 = 1.0f / 64.0f;
            const float inv4096 = inv64 * inv64;
            float4 rv = *(const float4*)&rs[c0];
            #pragma unroll
            for (int r = 0; r < 4; r++) {
                int i = r0 + r;
                float sgni = (i & 1) ? -1.f : 1.f;
                float4 xv = *(const float4*)&xin[i * 64 + c0];
                float2 a0 = unpk(Ea[r][0]), a1 = unpk(Ea[r][1]);
                float csv = cs[i] * inv64;
                float tci = sgni * ts * inv4096;
                float vx = xv.x + sgni * rv.x * inv64 + csv + tci;
                float vy = xv.y + sgni * rv.y * inv64 - csv - tci;
                float vz = xv.z + sgni * rv.z * inv64 + csv + tci;
                float vw = xv.w + sgni * rv.w * inv64 - csv - tci;
                float4 o;
                o.x = k0 + k1 * xv.x + k2q * (vx * vx + a0.x + Ff[r][0]);
                o.y = k0 + k1 * xv.y + k2q * (vy * vy + a0.y + Ff[r][1]);
                o.z = k0 + k1 * xv.z + k2q * (vz * vz + a1.x + Ff[r][2]);
                o.w = k0 + k1 * xv.w + k2q * (vw * vw + a1.y + Ff[r][3]);
                *(float4*)&outp[i * 64 + c0] = o;
            }
        }
        // No loop-end barrier needed: next P0 writes B0/Pr/Pc, whose last readers
        // (P3 for B0, P2a for Pr/Pc) are barrier-protected upstream.
    }
}

// Host-side taps (double precision, exact integer angle reduction; 64-periodic).
static double host_g(int t) {
    const double PI_D = 3.14159265358979323846;
    long long m = 2LL * t + 1;
    int r1 = (int)(((63LL * m) % 256 + 256) % 256); if (r1 >= 128) r1 -= 256;
    int r2 = (int)((m % 256 + 256) % 256);          if (r2 >= 128) r2 -= 256;
    return (sin(PI_D * r1 / 128.0) / sin(PI_D * r2 / 128.0)) / 64.0;
}

extern "C" void kernel_launch(void* const* d_in, const int* in_sizes, int n_in,
                              void* d_out, int out_size) {
    const float* x    = (const float*)d_in[0];
    const float* coef = (const float*)d_in[1];
    float* out = (float*)d_out;

    static TapTable tab;
    static bool tab_init = false;
    if (!tab_init) {
        for (int m = 0; m < 34; m++)
            for (int c = 0; c < 16; c++) {
                int s = 4 * c + 2 * m - 64;
                float g0 = (float)host_g(s);
                float g1 = (float)host_g(s + 1);
                float g2 = (float)host_g(s + 2);
                tab.e[m * 16 + c] = make_float4(g0, g1, g1, g2);
            }
        for (int i = 0; i < 127; i++) tab.sg[i] = (float)host_g(i - 63);
        tab.sg[127] = 0.f;
        tab_init = true;
    }

    zero_ctr_kernel<<<1, 1>>>();

    int smem_bytes = 3 * NB * (int)sizeof(float)
                   + 544 * 16
                   + (2 * 1088 + 4 * 64 + 4) * (int)sizeof(float);   // ~70.7 KB
    cudaFuncSetAttribute(uppolyact_kernel,
                         cudaFuncAttributeMaxDynamicSharedMemorySize, smem_bytes);

    int nimg = in_sizes[0] / 4096;   // 4096 images of 64x64
    uppolyact_kernel<<<444, 256, smem_bytes>>>(x, coef, out, tab, nimg);
}

// round 10
// speedup vs baseline: 1.1252x; 1.0794x over previous
#include <cuda_runtime.h>
#include <cmath>

#define PITCH 68
#define NB (64 * PITCH)   // 4352 floats per padded 64x64 buffer

typedef unsigned long long ull;

// Host-built tap tables, passed by value (~13.3 KB in kernel param space).
// d[m*8+rg]  = {g(s),g(s),g(s+1),g(s+1)},   s = 8*rg + 2*m - 64   (dup-quads, left)
// p[m*16+c]  = {g(s),g(s+1),g(s+1),g(s+2)}, s = 4*c  + 2*m - 64   (pair-quads, right)
struct TapParam { float4 d[288]; float4 p[544]; };

__device__ __forceinline__ ull f2x2(float lo, float hi) {
    ull r; asm("mov.b64 %0, {%1, %2};" : "=l"(r) : "f"(lo), "f"(hi)); return r;
}
__device__ __forceinline__ float2 unpk(ull v) {
    float2 r; asm("mov.b64 {%0, %1}, %2;" : "=f"(r.x), "=f"(r.y) : "l"(v)); return r;
}
__device__ __forceinline__ void ffma2(ull& d, ull a, ull b) {
    asm("fma.rn.f32x2 %0, %1, %2, %0;" : "+l"(d) : "l"(a), "l"(b));
}

// Left dup taps: t[w] = dup g(8rg - kb - 7 - SH + w), w in [0,15). 8 broadcast LDS.128.
// Entry e[j] = D[(m0+j)*8+rg] covers s0+2j (.x) and s0+2j+1 (.y), s0 = 8rg - kb - 8.
template<int SH>
__device__ __forceinline__ void load_ldtaps(ull t[15], const ulonglong2* __restrict__ D,
                                            int kb, int rg) {
    const ulonglong2* dp = D + (28 - (kb >> 1)) * 8 + rg;
    ulonglong2 e[8];
    #pragma unroll
    for (int j = 0; j < 8; j++) e[j] = dp[j * 8];
    #pragma unroll
    for (int w = 0; w < 15; w++) {
        if (SH == 0) t[w] = (w & 1) ? e[(w + 1) >> 1].x : e[w >> 1].y;
        else         t[w] = (w & 1) ? e[w >> 1].y       : e[w >> 1].x;
    }
}

// Right pair taps (identical to proven R5 loader): t[w] = pair(row u0+w), u0 = 57-SH-kb.
template<int SH>
__device__ __forceinline__ void load_rtaps(ull t[10], const ulonglong2* __restrict__ TU,
                                           int kb, int cg) {
    const ulonglong2* tp = TU + (28 - (kb >> 1)) * 16 + cg;
    ulonglong2 e[6];
    #pragma unroll
    for (int j = 0; j < (SH ? 5 : 6); j++) e[j] = tp[j * 16];
    #pragma unroll
    for (int w = 0; w < 10; w++) {
        if (SH) t[w] = (w & 1) ? e[w >> 1].y : e[w >> 1].x;
        else    t[w] = (w & 1) ? e[(w + 1) >> 1].x : e[w >> 1].y;
    }
}

// Left circulant, 8x4 tile, col-pair acc, MOV-free:
// acc[r][p] = {dst[8rg+r][c0+2p], dst[8rg+r][c0+2p+1]}, dst = sum_k g(i-k-SH) src[k][:]
template<int SH>
__device__ __forceinline__ void mm_left8(ull acc[8][2], const float* __restrict__ src,
                                         const ulonglong2* __restrict__ D,
                                         int rg, int c0) {
    #pragma unroll
    for (int r = 0; r < 8; r++) { acc[r][0] = 0ull; acc[r][1] = 0ull; }
    #pragma unroll 1
    for (int kb = 0; kb < 64; kb += 8) {
        ull t[15];
        load_ldtaps<SH>(t, D, kb, rg);
        #pragma unroll
        for (int q = 0; q < 8; q++) {
            ulonglong2 s = *(const ulonglong2*)&src[(kb + q) * PITCH + c0];
            #pragma unroll
            for (int r = 0; r < 8; r++) {
                ull a = t[r - q + 7];         // dup g((8rg+r)-(kb+q)-SH)
                ffma2(acc[r][0], a, s.x);
                ffma2(acc[r][1], a, s.y);
            }
        }
    }
}

// Right circulant^T, 8x4 tile, col-pair acc:
// acc[i][p] = {dst[r0+i][c0+2p], dst[r0+i][c0+2p+1]}, dst[i][m] = sum_k src[i][k] g(m-k-SH)
template<int SH>
__device__ __forceinline__ void mm_right8(ull acc[8][2], const float* __restrict__ src,
                                          const ulonglong2* __restrict__ TU,
                                          int r0, int cg) {
    #pragma unroll
    for (int r = 0; r < 8; r++) { acc[r][0] = 0ull; acc[r][1] = 0ull; }
    #pragma unroll 1
    for (int kb = 0; kb < 64; kb += 8) {
        ull t[10];
        load_rtaps<SH>(t, TU, kb, cg);
        #pragma unroll
        for (int i = 0; i < 8; i++) {
            float4 va = *(const float4*)&src[(r0 + i) * PITCH + kb];
            float4 vb = *(const float4*)&src[(r0 + i) * PITCH + kb + 4];
            float sv[8] = {va.x, va.y, va.z, va.w, vb.x, vb.y, vb.z, vb.w};
            #pragma unroll
            for (int q = 0; q < 8; q++) {
                ull sd = f2x2(sv[q], sv[q]);
                ffma2(acc[i][0], sd, t[7 - q]);   // pair(c0   - (kb+q) - SH)
                ffma2(acc[i][1], sd, t[9 - q]);   // pair(c0+2 - (kb+q) - SH)
            }
        }
    }
}

__device__ __forceinline__ void store8(float* __restrict__ dst, ull acc[8][2],
                                       int r0, int c0) {
    #pragma unroll
    for (int r = 0; r < 8; r++) {
        ulonglong2 o; o.x = acc[r][0]; o.y = acc[r][1];
        *(ulonglong2*)&dst[(r0 + r) * PITCH + c0] = o;
    }
}

__global__ void __launch_bounds__(128, 3)
uppolyact_kernel(const float* __restrict__ xg,
                 const float* __restrict__ coef,
                 float* __restrict__ outg,
                 const TapParam tab) {
    extern __shared__ float sm[];
    float* B0 = sm;            // x -> oo^2
    float* B1 = sm + NB;       // Gx -> oe^2 -> tmp
    float* B2 = sm + 2 * NB;   // xG^T -> eo^2
    ulonglong2* Dup = (ulonglong2*)(sm + 3 * NB);  // 288 entries
    ulonglong2* TU  = Dup + 288;                   // 544 entries
    float* Pr  = (float*)(TU + 544);   // 8 x 68
    float* Pc  = Pr + 544;             // 16 x 68
    float* rs  = Pc + 1088;            // 64
    float* cs  = rs + 64;              // 64
    float* rs1 = cs + 64;              // 64
    float* cs2 = rs1 + 64;             // 64
    float* tsp = cs2 + 64;             // 1

    const int tid = threadIdx.x;
    const int rg = tid >> 4, cg = tid & 15;
    const int r0 = rg << 3, c0 = cg << 2;
    const float* xin = xg + (size_t)blockIdx.x * 4096;
    float* outp = outg + (size_t)blockIdx.x * 4096;
    const float inv64 = 1.0f / 64.0f;

    const float k0 = __ldg(&coef[0]), k1 = __ldg(&coef[1]);
    const float k2q = 0.25f * __ldg(&coef[2]);

    // ---- P0: tables -> smem; load image; x rank-1 partials ----
    {
        const float4* dp = tab.d;  float4* dd = (float4*)Dup;
        #pragma unroll
        for (int i = tid; i < 288; i += 128) dd[i] = dp[i];
        const float4* pp = tab.p;  float4* pd = (float4*)TU;
        #pragma unroll
        for (int i = tid; i < 544; i += 128) pd[i] = pp[i];
    }
    {
        float4 xv[8];
        #pragma unroll
        for (int r = 0; r < 8; r++) {
            xv[r] = *(const float4*)&xin[(r0 + r) * 64 + c0];
            *(float4*)&B0[(r0 + r) * PITCH + c0] = xv[r];
        }
        float4 pr = make_float4(0.f, 0.f, 0.f, 0.f);   // alt-sum over 8 rows (r0 even)
        #pragma unroll
        for (int r = 0; r < 8; r++) {
            float sg = (r & 1) ? -1.f : 1.f;
            pr.x += sg * xv[r].x; pr.y += sg * xv[r].y;
            pr.z += sg * xv[r].z; pr.w += sg * xv[r].w;
        }
        *(float4*)&Pr[rg * 68 + c0] = pr;
        float pc[8];                                    // alt-sum over 4 cols (c0 even)
        #pragma unroll
        for (int r = 0; r < 8; r++)
            pc[r] = xv[r].x - xv[r].y + xv[r].z - xv[r].w;
        *(float4*)&Pc[cg * 68 + r0]     = make_float4(pc[0], pc[1], pc[2], pc[3]);
        *(float4*)&Pc[cg * 68 + r0 + 4] = make_float4(pc[4], pc[5], pc[6], pc[7]);
    }
    __syncthreads();

    // ---- P1: rs/cs reduce (tid<64) + a1 = Gx ; a2 = xG^T ----
    if (tid < 64) {
        float s = 0.f, t = 0.f;
        #pragma unroll
        for (int g = 0; g < 8; g++)  s += Pr[g * 68 + tid];
        #pragma unroll
        for (int g = 0; g < 16; g++) t += Pc[g * 68 + tid];
        rs[tid] = s; cs[tid] = t;
    }
    {
        ull a1[8][2];
        mm_left8<0>(a1, B0, Dup, rg, c0);
        store8(B1, a1, r0, c0);
        float pc[8];   // cs2 partials: alt col-sums of Gx per row
        #pragma unroll
        for (int r = 0; r < 8; r++) {
            float2 u = unpk(a1[r][0]), w = unpk(a1[r][1]);
            pc[r] = u.x - u.y + w.x - w.y;
        }
        *(float4*)&Pc[cg * 68 + r0]     = make_float4(pc[0], pc[1], pc[2], pc[3]);
        *(float4*)&Pc[cg * 68 + r0 + 4] = make_float4(pc[4], pc[5], pc[6], pc[7]);
    }
    {
        ull a2[8][2];
        mm_right8<0>(a2, B0, TU, r0, cg);
        store8(B2, a2, r0, c0);
        float4 pr = make_float4(0.f, 0.f, 0.f, 0.f);   // rs1 partials: alt row-sums of xG^T
        #pragma unroll
        for (int r = 0; r < 8; r++) {
            float sg = (r & 1) ? -1.f : 1.f;
            float2 u = unpk(a2[r][0]), w = unpk(a2[r][1]);
            pr.x += sg * u.x; pr.y += sg * u.y;
            pr.z += sg * w.x; pr.w += sg * w.y;
        }
        *(float4*)&Pr[rg * 68 + c0] = pr;
    }
    __syncthreads();

    // ---- P2a: rs1/cs2/ts reduces + a3 = (Gx)G^T ----
    if (tid < 64) {
        float s = 0.f, t = 0.f;
        #pragma unroll
        for (int g = 0; g < 8; g++)  s += Pr[g * 68 + tid];
        #pragma unroll
        for (int g = 0; g < 16; g++) t += Pc[g * 68 + tid];
        rs1[tid] = s; cs2[tid] = t;
    } else if (tid < 96) {
        int l = tid - 64;
        float v = rs[2 * l] - rs[2 * l + 1];
        #pragma unroll
        for (int o = 16; o > 0; o >>= 1) v += __shfl_xor_sync(~0u, v, o);
        if (l == 0) tsp[0] = v;
    }
    ull a3[8][2];
    mm_right8<0>(a3, B1, TU, r0, cg);
    __syncthreads();

    // ---- P2b: corrections + squares: B0<-oo^2 B1<-oe^2 B2<-eo^2 ----
    {
        float4 rv1 = *(const float4*)&rs1[c0];
        #pragma unroll
        for (int r = 0; r < 8; r++) {
            int i = r0 + r;
            float sgni = (i & 1) ? -1.f : 1.f;
            float cs2v = cs2[i] * inv64;
            int base = i * PITCH + c0;
            float4 v1 = *(float4*)&B1[base];   // Gx   -> oe
            float4 v2 = *(float4*)&B2[base];   // xG^T -> eo
            float2 o0 = unpk(a3[r][0]), o1 = unpk(a3[r][1]);
            float4 eo, oe, oo;
            eo.x = v2.x + sgni * rv1.x * inv64;
            eo.y = v2.y + sgni * rv1.y * inv64;
            eo.z = v2.z + sgni * rv1.z * inv64;
            eo.w = v2.w + sgni * rv1.w * inv64;
            oe.x = v1.x + cs2v;  oe.y = v1.y - cs2v;
            oe.z = v1.z + cs2v;  oe.w = v1.w - cs2v;
            oo.x = o0.x; oo.y = o0.y; oo.z = o1.x; oo.w = o1.y;
            eo.x *= eo.x; eo.y *= eo.y; eo.z *= eo.z; eo.w *= eo.w;
            oe.x *= oe.x; oe.y *= oe.y; oe.z *= oe.z; oe.w *= oe.w;
            oo.x *= oo.x; oo.y *= oo.y; oo.z *= oo.z; oo.w *= oo.w;
            *(float4*)&B2[base] = eo;
            *(float4*)&B1[base] = oe;
            *(float4*)&B0[base] = oo;
        }
    }
    __syncthreads();

    // ---- P3: tmp: B1 = oe^2 + oo^2 G'^T  (own-tile in-place) ----
    {
        ull acc[8][2];
        mm_right8<1>(acc, B0, TU, r0, cg);
        #pragma unroll
        for (int r = 0; r < 8; r++) {
            int base = (r0 + r) * PITCH + c0;
            float4 d = *(float4*)&B1[base];
            float2 a0 = unpk(acc[r][0]), a1 = unpk(acc[r][1]);
            d.x += a0.x;  d.y += a0.y;  d.z += a1.x;  d.w += a1.y;
            *(float4*)&B1[base] = d;
        }
    }
    __syncthreads();

    // ---- P4+P5: F = G'*tmp (left), E = eo^2 G'^T (right), final combine ----
    {
        ull Fa[8][2];
        mm_left8<1>(Fa, B1, Dup, rg, c0);
        ull Ea[8][2];
        mm_right8<1>(Ea, B2, TU, r0, cg);
        const float ts = tsp[0];
        const float inv4096 = inv64 * inv64;
        float4 rv = *(const float4*)&rs[c0];
        #pragma unroll
        for (int r = 0; r < 8; r++) {
            int i = r0 + r;
            float sgni = (i & 1) ? -1.f : 1.f;
            float4 xv = *(const float4*)&xin[i * 64 + c0];
            float2 f0 = unpk(Fa[r][0]), f1 = unpk(Fa[r][1]);
            float2 e0 = unpk(Ea[r][0]), e1 = unpk(Ea[r][1]);
            float csv = cs[i] * inv64;
            float tci = sgni * ts * inv4096;
            float vx = xv.x + sgni * rv.x * inv64 + csv + tci;
            float vy = xv.y + sgni * rv.y * inv64 - csv - tci;
            float vz = xv.z + sgni * rv.z * inv64 + csv + tci;
            float vw = xv.w + sgni * rv.w * inv64 - csv - tci;
            float4 o;
            o.x = k0 + k1 * xv.x + k2q * (vx * vx + e0.x + f0.x);
            o.y = k0 + k1 * xv.y + k2q * (vy * vy + e0.y + f0.y);
            o.z = k0 + k1 * xv.z + k2q * (vz * vz + e1.x + f1.x);
            o.w = k0 + k1 * xv.w + k2q * (vw * vw + e1.y + f1.y);
            *(float4*)&outp[i * 64 + c0] = o;
        }
    }
}

// Host-side taps (double precision, exact integer angle reduction; 64-periodic).
static double host_g(int t) {
    const double PI_D = 3.14159265358979323846;
    long long m = 2LL * t + 1;
    int r1 = (int)(((63LL * m) % 256 + 256) % 256); if (r1 >= 128) r1 -= 256;
    int r2 = (int)((m % 256 + 256) % 256);          if (r2 >= 128) r2 -= 256;
    return (sin(PI_D * r1 / 128.0) / sin(PI_D * r2 / 128.0)) / 64.0;
}

extern "C" void kernel_launch(void* const* d_in, const int* in_sizes, int n_in,
                              void* d_out, int out_size) {
    const float* x    = (const float*)d_in[0];
    const float* coef = (const float*)d_in[1];
    float* out = (float*)d_out;

    static TapParam tab;
    static bool tab_init = false;
    if (!tab_init) {
        for (int m = 0; m < 36; m++)
            for (int rg = 0; rg < 8; rg++) {
                int s = 8 * rg + 2 * m - 64;
                float g0 = (float)host_g(s), g1 = (float)host_g(s + 1);
                tab.d[m * 8 + rg] = make_float4(g0, g0, g1, g1);
            }
        for (int m = 0; m < 34; m++)
            for (int c = 0; c < 16; c++) {
                int s = 4 * c + 2 * m - 64;
                float g0 = (float)host_g(s);
                float g1 = (float)host_g(s + 1);
                float g2 = (float)host_g(s + 2);
                tab.p[m * 16 + c] = make_float4(g0, g1, g1, g2);
            }
        tab_init = true;
    }

    // 3 buffers + Dup(288x16B) + TU(544x16B) + Pr/Pc + scratch
    int smem_bytes = 3 * NB * (int)sizeof(float)
                   + (288 + 544) * 16
                   + (544 + 1088 + 4 * 64 + 4) * (int)sizeof(float);   // ~73.1 KB
    cudaFuncSetAttribute(uppolyact_kernel,
                         cudaFuncAttributeMaxDynamicSharedMemorySize, smem_bytes);

    int nimg = in_sizes[0] / 4096;   // 4096 images of 64x64
    uppolyact_kernel<<<nimg, 128, smem_bytes>>>(x, coef, out, tab);
}